// round 4
// baseline (speedup 1.0000x reference)
#include <cuda_runtime.h>
#include <cuda_bf16.h>
#include <mma.h>
#include <math.h>

using namespace nvcuda;

#define D      512
#define KWTA   128
#define MAXB   8192

// GEMM tiling
#define BM     128
#define BN     128
#define BK     32
#define LDAS   40                // A smem leading dim (bf16), 80B rows
#define LDBS   136               // B smem leading dim
#define LDE    132               // f32 epilogue staging leading dim
#define STAGE_E (BM * LDAS + BK * LDBS)          // 9472 bf16 per stage
#define PIPE_BYTES (3 * STAGE_E * 2)             // 56832
#define OFF_GATE   PIPE_BYTES                    // gate buffer (bf16, 128x128)
#define SMEM1      (PIPE_BYTES + BM * BN * 2)    // 89600
#define SMEM2      PIPE_BYTES

// ---------------- device scratch ----------------
__device__ __nv_bfloat16 g_Wb[D * D];
__device__ __nv_bfloat16 g_WTb[D * D];
__device__ __nv_bfloat16 g_V15b[D * D];          // 1.5 * V
__device__ __nv_bfloat16 g_Rb[D * D];
__device__ __nv_bfloat16 g_Rgb[D * D];
__device__ __nv_bfloat16 g_Lb[D * D];

__device__ __nv_bfloat16 g_phix[MAXB * D];
__device__ __nv_bfloat16 g_bub[MAXB * D];
__device__ __nv_bfloat16 g_ctx[MAXB * D];
__device__ __nv_bfloat16 g_phic[MAXB * D];
__device__ __nv_bfloat16 g_phid[MAXB * D];
__device__ __nv_bfloat16 g_err[MAXB * D];
__device__ __nv_bfloat16 g_RG[MAXB * D];
__device__ __nv_bfloat16 g_g[MAXB * D];
__device__ float g_P1[MAXB * D];

__device__ float g_part[(MAXB / BM) * (D / BN)];
__device__ float g_scalef;

// ---------------- weight conversion ----------------
__global__ void convert_kernel(const float* __restrict__ W, const float* __restrict__ V,
                               const float* __restrict__ R, const float* __restrict__ Rg,
                               const float* __restrict__ L) {
    int n = D * D;
    for (int idx = blockIdx.x * blockDim.x + threadIdx.x; idx < n; idx += gridDim.x * blockDim.x) {
        int i = idx >> 9, j = idx & 511;
        float w = W[idx];
        g_Wb[idx]        = __float2bfloat16(w);
        g_WTb[j * D + i] = __float2bfloat16(w);
        g_V15b[idx]      = __float2bfloat16(1.5f * V[idx]);
        g_Rb[idx]        = __float2bfloat16(R[idx]);
        g_Rgb[idx]       = __float2bfloat16(Rg[idx]);
        g_Lb[idx]        = __float2bfloat16(L[idx]);
    }
}

// ---------------- exact register k-WTA (top-128 of 512, stable ties) -------
__device__ __forceinline__ void kwta_reg(const float v[16], float m[16]) {
    int lane = threadIdx.x & 31;
    unsigned u[16];
#pragma unroll
    for (int j = 0; j < 16; j++) {
        unsigned b = __float_as_uint(v[j]);
        u[j] = (b & 0x80000000u) ? ~b : (b | 0x80000000u);
    }
    unsigned prefix = 0;
    for (int bit = 31; bit >= 0; --bit) {
        unsigned probe = prefix | (1u << bit);
        int c = 0;
#pragma unroll
        for (int j = 0; j < 16; j++) c += (u[j] >= probe);
        c = __reduce_add_sync(0xffffffffu, c);
        if (c >= KWTA) prefix = probe;
    }
    int cg = 0;
#pragma unroll
    for (int j = 0; j < 16; j++) cg += (u[j] > prefix);
    cg = __reduce_add_sync(0xffffffffu, cg);
    int remk = KWTA - cg;
    unsigned lmask = (1u << lane) - 1u;
    int running = 0;
#pragma unroll
    for (int j = 0; j < 16; j++) {
        bool eq = (u[j] == prefix);
        unsigned beq = __ballot_sync(0xffffffffu, eq);
        bool inc = (u[j] > prefix) || (eq && (running + __popc(beq & lmask)) < remk);
        running += __popc(beq);
        m[j] = inc ? 1.0f : 0.0f;
    }
}

// ---------------- elementwise precompute (one warp per batch row) ----------
__global__ void __launch_bounds__(256) elemwise_kernel(
    const float* __restrict__ x, const float* __restrict__ xt1,
    const float* __restrict__ xt2, const float* __restrict__ xt3,
    const float* __restrict__ bu) {
    const int warp = threadIdx.x >> 5, lane = threadIdx.x & 31;
    const size_t base = ((size_t)blockIdx.x * 8 + warp) * D;
    const float INV_SQRT2 = 0.70710678118654752440f;
    const float INV_SQRT2PI = 0.39894228040143267794f;

    float v[16], m[16];
#pragma unroll
    for (int j = 0; j < 16; j++) v[j] = x[base + lane + 32 * j];
    kwta_reg(v, m);
#pragma unroll
    for (int j = 0; j < 16; j++) {
        size_t idx = base + lane + 32 * j;
        float val = v[j];
        float cdf = 0.5f * (1.0f + erff(val * INV_SQRT2));
        float pdf = __expf(-0.5f * val * val) * INV_SQRT2PI;
        g_phix[idx] = __float2bfloat16(val * cdf * m[j]);
        g_phid[idx] = __float2bfloat16((cdf + val * pdf) * m[j]);
        g_bub[idx]  = __float2bfloat16(bu[idx]);
    }
    float c[16];
#pragma unroll
    for (int j = 0; j < 16; j++) {
        size_t idx = base + lane + 32 * j;
        c[j] = 0.5f * xt1[idx] + 0.3f * xt2[idx] + 0.2f * xt3[idx];
    }
    kwta_reg(c, m);
#pragma unroll
    for (int j = 0; j < 16; j++) {
        size_t idx = base + lane + 32 * j;
        float val = c[j];
        g_ctx[idx] = __float2bfloat16(val);
        float cdf = 0.5f * (1.0f + erff(val * INV_SQRT2));
        g_phic[idx] = __float2bfloat16(val * cdf * m[j]);
    }
}

// ---------------- cp.async helpers ----------------
__device__ __forceinline__ void cp16(void* s, const void* g) {
    unsigned sa = (unsigned)__cvta_generic_to_shared(s);
    asm volatile("cp.async.cg.shared.global [%0], [%1], 16;" :: "r"(sa), "l"(g));
}

// Load one BK-stage. ks in [0, nk). For concat GEMMs (nk=32), the second half
// reads A1/B1 with local k offset.
__device__ __forceinline__ void load_stage(__nv_bfloat16* stage,
                                           const __nv_bfloat16* A0, const __nv_bfloat16* B0,
                                           const __nv_bfloat16* A1, const __nv_bfloat16* B1,
                                           int ks, int tid) {
    const __nv_bfloat16* Ag = (ks >= 16) ? A1 : A0;
    const __nv_bfloat16* Bg = (ks >= 16) ? B1 : B0;
    int k0 = (ks & 15) * BK;
    __nv_bfloat16* As = stage;
    __nv_bfloat16* Bs = stage + BM * LDAS;
#pragma unroll
    for (int t = 0; t < 2; t++) {
        int task = tid + t * 256;
        int arow = task >> 2, ach = task & 3;
        cp16(As + arow * LDAS + ach * 8, Ag + (size_t)arow * D + k0 + ach * 8);
        int brow = task >> 4, bch = task & 15;
        cp16(Bs + brow * LDBS + bch * 8, Bg + (size_t)(k0 + brow) * D + bch * 8);
    }
}

// ---------------- pipelined 128x128 GEMM core (accumulates into acc) -------
__device__ __forceinline__ void run_gemm(
    const __nv_bfloat16* A0, const __nv_bfloat16* B0,
    const __nv_bfloat16* A1, const __nv_bfloat16* B1,
    int nk, __nv_bfloat16* smem, int tid, int wm, int wn,
    wmma::fragment<wmma::accumulator, 16, 16, 16, float> acc[4][2]) {
    load_stage(smem + 0 * STAGE_E, A0, B0, A1, B1, 0, tid);
    asm volatile("cp.async.commit_group;" ::: "memory");
    load_stage(smem + 1 * STAGE_E, A0, B0, A1, B1, 1, tid);
    asm volatile("cp.async.commit_group;" ::: "memory");

    for (int ki = 0; ki < nk; ki++) {
        asm volatile("cp.async.wait_group 1;" ::: "memory");
        __syncthreads();
        __nv_bfloat16* As = smem + (ki % 3) * STAGE_E;
        __nv_bfloat16* Bs = As + BM * LDAS;
#pragma unroll
        for (int kk = 0; kk < BK; kk += 16) {
            wmma::fragment<wmma::matrix_a, 16, 16, 16, __nv_bfloat16, wmma::row_major> af[4];
            wmma::fragment<wmma::matrix_b, 16, 16, 16, __nv_bfloat16, wmma::row_major> bf_[2];
#pragma unroll
            for (int i = 0; i < 4; i++)
                wmma::load_matrix_sync(af[i], As + (wm * 64 + i * 16) * LDAS + kk, LDAS);
#pragma unroll
            for (int j = 0; j < 2; j++)
                wmma::load_matrix_sync(bf_[j], Bs + kk * LDBS + wn * 32 + j * 16, LDBS);
#pragma unroll
            for (int i = 0; i < 4; i++)
#pragma unroll
                for (int j = 0; j < 2; j++)
                    wmma::mma_sync(acc[i][j], af[i], bf_[j], acc[i][j]);
        }
        if (ki + 2 < nk) load_stage(smem + ((ki + 2) % 3) * STAGE_E, A0, B0, A1, B1, ki + 2, tid);
        asm volatile("cp.async.commit_group;" ::: "memory");
    }
    asm volatile("cp.async.wait_group 0;" ::: "memory");
    __syncthreads();
}

// ---------------- stage 1: err | P1 | rec*gate ----------------
// z=0: err = bub - (phix@W + b_out)                        -> g_err bf16
// z=1: P1 = phix@L + bu@(1.5V) + 1.5 b_in + 3 td - 5.5 x - 1e-6 sign(x) -> f32
// z=2: gate = sigmoid(ctx@Rg) [smem]; RG = (phic@R)*gate   -> g_RG bf16
__global__ void __launch_bounds__(256) stage1_kernel(
    const float* __restrict__ b_in, const float* __restrict__ b_out,
    const float* __restrict__ td, const float* __restrict__ x) {
    extern __shared__ unsigned char smem_raw[];
    __nv_bfloat16* smem = (__nv_bfloat16*)smem_raw;
    __nv_bfloat16* gatebuf = (__nv_bfloat16*)(smem_raw + OFF_GATE);
    float* Es = (float*)smem_raw;

    const int tid = threadIdx.x, wid = tid >> 5;
    const int wm = wid >> 2, wn = wid & 3;
    const int z = blockIdx.z;
    const int n0 = blockIdx.x * BN, m0 = blockIdx.y * BM;

    wmma::fragment<wmma::accumulator, 16, 16, 16, float> acc[4][2];
#pragma unroll
    for (int i = 0; i < 4; i++)
#pragma unroll
        for (int j = 0; j < 2; j++) wmma::fill_fragment(acc[i][j], 0.0f);

    if (z == 0) {
        run_gemm(g_phix + (size_t)m0 * D, g_Wb + n0, 0, 0, 16, smem, tid, wm, wn, acc);
#pragma unroll 1
        for (int half = 0; half < 2; half++) {
            __syncthreads();
            if (wm == half)
#pragma unroll
                for (int i = 0; i < 4; i++)
#pragma unroll
                    for (int j = 0; j < 2; j++)
                        wmma::store_matrix_sync(Es + (i * 16) * LDE + wn * 32 + j * 16,
                                                acc[i][j], LDE, wmma::mem_row_major);
            __syncthreads();
#pragma unroll 4
            for (int t = 0; t < 32; t++) {
                int idx = t * 256 + tid;
                int r = idx >> 7, c = idx & 127;
                size_t gi = (size_t)(m0 + half * 64 + r) * D + n0 + c;
                float pred = Es[r * LDE + c] + b_out[n0 + c];
                g_err[gi] = __float2bfloat16(__bfloat162float(g_bub[gi]) - pred);
            }
        }
    } else if (z == 1) {
        run_gemm(g_phix + (size_t)m0 * D, g_Lb + n0,
                 g_bub + (size_t)m0 * D, g_V15b + n0, 32, smem, tid, wm, wn, acc);
#pragma unroll 1
        for (int half = 0; half < 2; half++) {
            __syncthreads();
            if (wm == half)
#pragma unroll
                for (int i = 0; i < 4; i++)
#pragma unroll
                    for (int j = 0; j < 2; j++)
                        wmma::store_matrix_sync(Es + (i * 16) * LDE + wn * 32 + j * 16,
                                                acc[i][j], LDE, wmma::mem_row_major);
            __syncthreads();
#pragma unroll 4
            for (int t = 0; t < 32; t++) {
                int idx = t * 256 + tid;
                int r = idx >> 7, c = idx & 127;
                size_t gi = (size_t)(m0 + half * 64 + r) * D + n0 + c;
                float xv = x[gi];
                float sgn = (xv > 0.0f) ? 1.0f : ((xv < 0.0f) ? -1.0f : 0.0f);
                g_P1[gi] = Es[r * LDE + c] + 1.5f * b_in[n0 + c] + 3.0f * td[gi]
                           - 5.5f * xv - 1e-6f * sgn;
            }
        }
    } else {
        // pass 0: gate
        run_gemm(g_ctx + (size_t)m0 * D, g_Rgb + n0, 0, 0, 16, smem, tid, wm, wn, acc);
#pragma unroll 1
        for (int half = 0; half < 2; half++) {
            __syncthreads();
            if (wm == half)
#pragma unroll
                for (int i = 0; i < 4; i++)
#pragma unroll
                    for (int j = 0; j < 2; j++)
                        wmma::store_matrix_sync(Es + (i * 16) * LDE + wn * 32 + j * 16,
                                                acc[i][j], LDE, wmma::mem_row_major);
            __syncthreads();
#pragma unroll 4
            for (int t = 0; t < 32; t++) {
                int idx = t * 256 + tid;
                int r = idx >> 7, c = idx & 127;
                float v = Es[r * LDE + c];
                gatebuf[(half * 64 + r) * BN + c] = __float2bfloat16(1.0f / (1.0f + __expf(-v)));
            }
        }
        __syncthreads();
        // pass 1: rec, multiply by gate
#pragma unroll
        for (int i = 0; i < 4; i++)
#pragma unroll
            for (int j = 0; j < 2; j++) wmma::fill_fragment(acc[i][j], 0.0f);
        run_gemm(g_phic + (size_t)m0 * D, g_Rb + n0, 0, 0, 16, smem, tid, wm, wn, acc);
#pragma unroll 1
        for (int half = 0; half < 2; half++) {
            __syncthreads();
            if (wm == half)
#pragma unroll
                for (int i = 0; i < 4; i++)
#pragma unroll
                    for (int j = 0; j < 2; j++)
                        wmma::store_matrix_sync(Es + (i * 16) * LDE + wn * 32 + j * 16,
                                                acc[i][j], LDE, wmma::mem_row_major);
            __syncthreads();
#pragma unroll 4
            for (int t = 0; t < 32; t++) {
                int idx = t * 256 + tid;
                int r = idx >> 7, c = idx & 127;
                size_t gi = (size_t)(m0 + half * 64 + r) * D + n0 + c;
                float gate = __bfloat162float(gatebuf[(half * 64 + r) * BN + c]);
                g_RG[gi] = __float2bfloat16(Es[r * LDE + c] * gate);
            }
        }
    }
}

// ---------------- stage 2: fb = err@W^T; g = fb*phid + P1 + RG -------------
__global__ void __launch_bounds__(256) stage2_kernel() {
    extern __shared__ unsigned char smem_raw[];
    __nv_bfloat16* smem = (__nv_bfloat16*)smem_raw;
    float* Es = (float*)smem_raw;
    __shared__ float red[256];

    const int tid = threadIdx.x, wid = tid >> 5;
    const int wm = wid >> 2, wn = wid & 3;
    const int n0 = blockIdx.x * BN, m0 = blockIdx.y * BM;

    wmma::fragment<wmma::accumulator, 16, 16, 16, float> acc[4][2];
#pragma unroll
    for (int i = 0; i < 4; i++)
#pragma unroll
        for (int j = 0; j < 2; j++) wmma::fill_fragment(acc[i][j], 0.0f);

    run_gemm(g_err + (size_t)m0 * D, g_WTb + n0, 0, 0, 16, smem, tid, wm, wn, acc);

    float ss = 0.0f;
#pragma unroll 1
    for (int half = 0; half < 2; half++) {
        __syncthreads();
        if (wm == half)
#pragma unroll
            for (int i = 0; i < 4; i++)
#pragma unroll
                for (int j = 0; j < 2; j++)
                    wmma::store_matrix_sync(Es + (i * 16) * LDE + wn * 32 + j * 16,
                                            acc[i][j], LDE, wmma::mem_row_major);
        __syncthreads();
#pragma unroll 4
        for (int t = 0; t < 32; t++) {
            int idx = t * 256 + tid;
            int r = idx >> 7, c = idx & 127;
            size_t gi = (size_t)(m0 + half * 64 + r) * D + n0 + c;
            float g = Es[r * LDE + c] * __bfloat162float(g_phid[gi])
                      + g_P1[gi] + __bfloat162float(g_RG[gi]);
            g_g[gi] = __float2bfloat16(g);
            ss += g * g;
        }
    }
    red[tid] = ss;
    __syncthreads();
    for (int o = 128; o > 0; o >>= 1) {
        if (tid < o) red[tid] += red[tid + o];
        __syncthreads();
    }
    if (tid == 0) g_part[blockIdx.y * gridDim.x + blockIdx.x] = red[0];
}

// ---------------- global norm -> clip scale ----------------
__global__ void reduce_scale_kernel(const int* __restrict__ step_i, int nparts) {
    __shared__ float red[256];
    float s = 0.0f;
    for (int i = threadIdx.x; i < nparts; i += 256) s += g_part[i];
    red[threadIdx.x] = s;
    __syncthreads();
    for (int o = 128; o > 0; o >>= 1) {
        if (threadIdx.x < o) red[threadIdx.x] += red[threadIdx.x + o];
        __syncthreads();
    }
    if (threadIdx.x == 0) {
        float eta = 0.8f / (1.0f + 0.1f * (float)step_i[0]);
        float cc = 0.5f * eta;                   // TAU * eta
        float n = cc * sqrtf(red[0]);
        float sc = (n > 1.0f) ? (1.0f / (n + 1e-8f)) : 1.0f;
        g_scalef = cc * sc;
    }
}

// ---------------- finalize: x_new = clip(x + g*scale, -5, 5) ----------------
__global__ void finalize_kernel(const float* __restrict__ x, float* __restrict__ out, int n2) {
    float f = g_scalef;
    const float2* x2 = (const float2*)x;
    const __nv_bfloat162* gg = (const __nv_bfloat162*)g_g;
    float2* o2 = (float2*)out;
    for (int i = blockIdx.x * blockDim.x + threadIdx.x; i < n2; i += gridDim.x * blockDim.x) {
        float2 xv = x2[i];
        float2 gv = __bfloat1622float2(gg[i]);
        float2 o;
        o.x = fminf(5.0f, fmaxf(-5.0f, xv.x + gv.x * f));
        o.y = fminf(5.0f, fmaxf(-5.0f, xv.y + gv.y * f));
        o2[i] = o;
    }
}

extern "C" void kernel_launch(void* const* d_in, const int* in_sizes, int n_in,
                              void* d_out, int out_size) {
    const float* bu    = (const float*)d_in[0];
    const float* td    = (const float*)d_in[1];
    const float* x     = (const float*)d_in[2];
    const float* xt1   = (const float*)d_in[3];
    const float* xt2   = (const float*)d_in[4];
    const float* xt3   = (const float*)d_in[5];
    const float* V     = (const float*)d_in[6];
    const float* b_in  = (const float*)d_in[7];
    const float* W     = (const float*)d_in[8];
    const float* b_out = (const float*)d_in[9];
    const float* R     = (const float*)d_in[10];
    const float* Rg    = (const float*)d_in[11];
    const float* L     = (const float*)d_in[12];
    const int*   step  = (const int*)d_in[13];

    int Btot = in_sizes[2] / D;
    if (Btot > MAXB) Btot = MAXB;
    int mtiles = Btot / BM;             // 64

    cudaFuncSetAttribute(stage1_kernel, cudaFuncAttributeMaxDynamicSharedMemorySize, SMEM1);
    cudaFuncSetAttribute(stage2_kernel, cudaFuncAttributeMaxDynamicSharedMemorySize, SMEM2);

    convert_kernel<<<128, 256>>>(W, V, R, Rg, L);
    elemwise_kernel<<<Btot / 8, 256>>>(x, xt1, xt2, xt3, bu);
    stage1_kernel<<<dim3(D / BN, mtiles, 3), 256, SMEM1>>>(b_in, b_out, td, x);
    stage2_kernel<<<dim3(D / BN, mtiles), 256, SMEM2>>>();
    reduce_scale_kernel<<<1, 256>>>(step, mtiles * (D / BN));
    finalize_kernel<<<1024, 256>>>(x, (float*)d_out, Btot * D / 2);
}